// round 3
// baseline (speedup 1.0000x reference)
#include <cuda_runtime.h>
#include <math.h>
#include <stdint.h>

#define Bb 128
#define Ss 1024
#define Dd 512
#define Nn 784

#define TN 56                    // n-tile width (784 = 14*56; 56 floats = 224B, 16B-aligned rows)
#define NTILES (Nn / TN)         // 14
#define TILE_FLOATS (Dd * TN)    // 28672
#define ATTN_THREADS 1024        // 32 warps; warp w owns d-rows [16w, 16w+16)

// ---------------- scratch (no allocations allowed) ----------------
__device__ float g_w[Bb * Dd];       // fused logit weights per (b,d)
__device__ float g_pooled[Bb * Dd];  // attention-pooled features

// ---------------- cp.async helpers ----------------
__device__ __forceinline__ void cp_async16(uint32_t smem_addr, const void* gptr) {
    asm volatile("cp.async.cg.shared.global [%0], [%1], 16;\n" ::"r"(smem_addr), "l"(gptr));
}
__device__ __forceinline__ void cp_commit() { asm volatile("cp.async.commit_group;\n"); }
template <int N>
__device__ __forceinline__ void cp_wait() { asm volatile("cp.async.wait_group %0;\n" ::"n"(N)); }

// ================= K1: fused w-GEMM =================
// grid (Dd/32, Bb/32) = (16,4), block (16,16).
// q = in_state @ Wq^T (32x32 tile); u1/u2 recomputed per-CTA for its 32 cols;
// w[r,c] = u1[c]*(q[r,c] + bq[c]) + u2[c]
__global__ void gemm_w(const float* __restrict__ A,   // in_state [B,S]
                       const float* __restrict__ Bm,  // Wq [D,S]
                       const float* __restrict__ bq,  // [D]
                       const float* __restrict__ Wc,  // [D,2D]
                       const float* __restrict__ Wa,  // [D]
                       float* __restrict__ W) {       // g_w [B,D]
    __shared__ float As[32][33];
    __shared__ float Bs[32][33];
    __shared__ float su1[8][32], su2[8][32];
    __shared__ float sU1[32], sU2[32];

    int tx = threadIdx.x, ty = threadIdx.y;
    int t = ty * 16 + tx;
    int row0 = blockIdx.y * 32, col0 = blockIdx.x * 32;

    // ---- u recompute for this CTA's 32 columns ----
    {
        int c = t & 31, g = t >> 5;  // 8 groups of 64 d-rows
        float u1p = 0.f, u2p = 0.f;
        int dbeg = g * 64;
#pragma unroll 4
        for (int d = dbeg; d < dbeg + 64; d++) {
            float wa = Wa[d];
            const float* wcrow = Wc + (size_t)d * (2 * Dd);
            u1p += wa * wcrow[col0 + c];
            u2p += wa * wcrow[Dd + col0 + c];
        }
        su1[g][c] = u1p;
        su2[g][c] = u2p;
    }
    __syncthreads();
    if (t < 64) {
        int c = t & 31;
        float s = 0.f;
        if (t < 32) {
#pragma unroll
            for (int g = 0; g < 8; g++) s += su1[g][c];
            sU1[c] = s;
        } else {
#pragma unroll
            for (int g = 0; g < 8; g++) s += su2[g][c];
            sU2[c] = s;
        }
    }

    // ---- q GEMM: 32x32 tile over K=1024 ----
    float acc00 = 0.f, acc01 = 0.f, acc10 = 0.f, acc11 = 0.f;
    for (int k0 = 0; k0 < Ss; k0 += 32) {
        __syncthreads();
#pragma unroll
        for (int i = t; i < 32 * 32; i += 256) {
            int r = i >> 5, c = i & 31;
            As[r][c] = A[(size_t)(row0 + r) * Ss + k0 + c];
            Bs[r][c] = Bm[(size_t)(col0 + r) * Ss + k0 + c];
        }
        __syncthreads();
#pragma unroll
        for (int kk = 0; kk < 32; kk++) {
            float a0 = As[ty * 2][kk], a1 = As[ty * 2 + 1][kk];
            float b0 = Bs[tx * 2][kk], b1 = Bs[tx * 2 + 1][kk];
            acc00 += a0 * b0; acc01 += a0 * b1;
            acc10 += a1 * b0; acc11 += a1 * b1;
        }
    }
    __syncthreads();

    int r0 = row0 + ty * 2, c0l = tx * 2;
    float v[2][2] = {{acc00, acc01}, {acc10, acc11}};
#pragma unroll
    for (int i = 0; i < 2; i++)
#pragma unroll
        for (int j = 0; j < 2; j++) {
            int cl = c0l + j;
            float q = v[i][j] + bq[col0 + cl];
            W[(size_t)(r0 + i) * Dd + col0 + cl] = sU1[cl] * q + sU2[cl];
        }
}

// ================= K2: single-pass flash attention =================
// One CTA per batch; image[b] read exactly once (14 double-buffered tiles).
// logits[n] = sum_d w[b,d]*img[d,n]; online softmax; pooled[d] = sum_n attn[n]*img[d,n].
__global__ __launch_bounds__(ATTN_THREADS, 1) void attn_flash(
    const float* __restrict__ image, const float* __restrict__ w) {
    extern __shared__ float smem[];
    float* bufs  = smem;                       // 2 * TILE_FLOATS
    float* spart = smem + 2 * TILE_FLOATS;     // 8 * 56 partial-logit rows
    float* sp    = spart + 8 * TN;             // 56 exp weights
    float* sctl  = sp + TN;                    // [0]=scale, [1]=Z

    const int b = blockIdx.x;
    const int tid = threadIdx.x;
    const int lane = tid & 31;
    const int warp = tid >> 5;  // 0..31
    const float* imgb = image + (size_t)b * Dd * Nn;
    const uint32_t smem_base = (uint32_t)__cvta_generic_to_shared(bufs);

    // lane l (<16) holds w[b, warp*16 + l]
    float swv = (lane < 16) ? w[b * Dd + warp * 16 + lane] : 0.f;

    float acc[16];
#pragma unroll
    for (int i = 0; i < 16; i++) acc[i] = 0.f;
    float m = -INFINITY, Zl = 0.f;

    // prologue: tile 0 -> buf 0
    for (int f = tid; f < TILE_FLOATS / 4; f += ATTN_THREADS) {
        int row = f / (TN / 4);
        int seg = f % (TN / 4);
        cp_async16(smem_base + (uint32_t)(row * TN + seg * 4) * 4,
                   (const char*)imgb + ((size_t)row * Nn + seg * 4) * 4);
    }
    cp_commit();

    for (int t = 0; t < NTILES; t++) {
        const float* cur = bufs + (t & 1) * TILE_FLOATS;

        if (t + 1 < NTILES) {
            uint32_t dst = smem_base + (uint32_t)(((t + 1) & 1) * TILE_FLOATS) * 4;
            const char* gbase = (const char*)(imgb + (t + 1) * TN);
            for (int f = tid; f < TILE_FLOATS / 4; f += ATTN_THREADS) {
                int row = f / (TN / 4);
                int seg = f % (TN / 4);
                cp_async16(dst + (uint32_t)(row * TN + seg * 4) * 4,
                           gbase + ((size_t)row * Nn + seg * 4) * 4);
            }
            cp_commit();
            cp_wait<1>();
        } else {
            cp_wait<0>();
        }
        __syncthreads();  // tile t resident

        // ---- per-warp partial logits over its 16 d-rows ----
        const float* wrows = cur + warp * 16 * TN;
        float a0 = 0.f, a1 = 0.f;
#pragma unroll
        for (int i = 0; i < 16; i++) {
            float wd = __shfl_sync(0xffffffffu, swv, i);
            a0 += wd * wrows[i * TN + lane];
            if (lane < 24) a1 += wd * wrows[i * TN + 32 + lane];
        }

        // ---- owner-exclusive reduction tree into spart[8][56] ----
        float* prow = spart + (warp & 7) * TN;
        if (warp < 8) {
            prow[lane] = a0;
            if (lane < 24) prow[32 + lane] = a1;
        }
        __syncthreads();
        if (warp >= 8 && warp < 16) {
            prow[lane] += a0;
            if (lane < 24) prow[32 + lane] += a1;
        }
        __syncthreads();
        if (warp >= 16 && warp < 24) {
            prow[lane] += a0;
            if (lane < 24) prow[32 + lane] += a1;
        }
        __syncthreads();
        if (warp >= 24) {
            prow[lane] += a0;
            if (lane < 24) prow[32 + lane] += a1;
        }
        __syncthreads();

        // ---- online softmax (warp 0 sums the 8 rows in registers) ----
        if (warp == 0) {
            float v0 = 0.f, v1 = 0.f;
#pragma unroll
            for (int r = 0; r < 8; r++) {
                v0 += spart[r * TN + lane];
                if (lane < 24) v1 += spart[r * TN + 32 + lane];
            }
            float l1v = (lane < 24) ? v1 : -INFINITY;
            float tmax = fmaxf(v0, l1v);
#pragma unroll
            for (int o = 16; o; o >>= 1) tmax = fmaxf(tmax, __shfl_xor_sync(0xffffffffu, tmax, o));
            float newm = fmaxf(m, tmax);
            float e0 = __expf(v0 - newm);
            float e1 = (lane < 24) ? __expf(v1 - newm) : 0.f;
            sp[lane] = e0;
            if (lane < 24) sp[32 + lane] = e1;
            float ts = e0 + e1;
#pragma unroll
            for (int o = 16; o; o >>= 1) ts += __shfl_xor_sync(0xffffffffu, ts, o);
            float sc = __expf(m - newm);
            Zl = Zl * sc + ts;
            m = newm;
            if (lane == 0) sctl[0] = sc;
        }
        __syncthreads();

        // ---- pooled accumulate (lane-distributed, rescale-on-the-fly) ----
        float sc = sctl[0];
        float p0 = sp[lane];
        float p1 = (lane < 24) ? sp[32 + lane] : 0.f;
#pragma unroll
        for (int i = 0; i < 16; i++) {
            float v = acc[i] * sc;
            v += p0 * wrows[i * TN + lane];
            if (lane < 24) v += p1 * wrows[i * TN + 32 + lane];
            acc[i] = v;
        }
        __syncthreads();  // cur fully consumed before prefetch t+2 overwrites it
    }

    if (warp == 0 && lane == 0) sctl[1] = Zl;
    __syncthreads();
    const float invZ = 1.f / sctl[1];

#pragma unroll
    for (int i = 0; i < 16; i++) {
        float v = acc[i];
#pragma unroll
        for (int o = 16; o; o >>= 1) v += __shfl_xor_sync(0xffffffffu, v, o);
        if (lane == 0) g_pooled[b * Dd + warp * 16 + i] = v * invZ;
    }
}

// ================= K3: out = pooled @ Wo^T + bo =================
// grid (Ss/32, Bb/32) = (32,4) = 128 CTAs, block (16,16), K=512, bias epilogue.
__global__ void gemm_out(const float* __restrict__ A,   // pooled [B,D]
                         const float* __restrict__ Bm,  // Wo [S,D]
                         const float* __restrict__ bo,  // [S]
                         float* __restrict__ C) {       // out [B,S]
    __shared__ float As[32][33];
    __shared__ float Bs[32][33];
    int tx = threadIdx.x, ty = threadIdx.y;
    int t = ty * 16 + tx;
    int row0 = blockIdx.y * 32, col0 = blockIdx.x * 32;
    float acc00 = 0.f, acc01 = 0.f, acc10 = 0.f, acc11 = 0.f;

    for (int k0 = 0; k0 < Dd; k0 += 32) {
#pragma unroll
        for (int i = t; i < 32 * 32; i += 256) {
            int r = i >> 5, c = i & 31;
            As[r][c] = A[(size_t)(row0 + r) * Dd + k0 + c];
            Bs[r][c] = Bm[(size_t)(col0 + r) * Dd + k0 + c];
        }
        __syncthreads();
#pragma unroll
        for (int kk = 0; kk < 32; kk++) {
            float a0 = As[ty * 2][kk], a1 = As[ty * 2 + 1][kk];
            float b0 = Bs[tx * 2][kk], b1 = Bs[tx * 2 + 1][kk];
            acc00 += a0 * b0; acc01 += a0 * b1;
            acc10 += a1 * b0; acc11 += a1 * b1;
        }
        __syncthreads();
    }
    int r0 = row0 + ty * 2, c0 = col0 + tx * 2;
    C[(size_t)r0 * Ss + c0]           = acc00 + bo[c0];
    C[(size_t)r0 * Ss + c0 + 1]       = acc01 + bo[c0 + 1];
    C[(size_t)(r0 + 1) * Ss + c0]     = acc10 + bo[c0];
    C[(size_t)(r0 + 1) * Ss + c0 + 1] = acc11 + bo[c0 + 1];
}

// ---------------- launcher (3 graph nodes) ----------------
extern "C" void kernel_launch(void* const* d_in, const int* in_sizes, int n_in,
                              void* d_out, int out_size) {
    const float* in_state = (const float*)d_in[0];  // [B, S]
    const float* image    = (const float*)d_in[1];  // [B, D, N]
    const float* Wq       = (const float*)d_in[2];  // [D, S]
    const float* bq       = (const float*)d_in[3];  // [D]
    const float* Wc       = (const float*)d_in[4];  // [D, 2D]
    // d_in[5] = bc (cancels in softmax)
    const float* Wa       = (const float*)d_in[6];  // [1, D]
    // d_in[7] = ba (cancels in softmax)
    const float* Wo       = (const float*)d_in[8];  // [S, D]
    const float* bo       = (const float*)d_in[9];  // [S]
    float* out = (float*)d_out;                     // [B, S]

    float* w_ptr;      cudaGetSymbolAddress((void**)&w_ptr, g_w);
    float* pooled_ptr; cudaGetSymbolAddress((void**)&pooled_ptr, g_pooled);

    static bool attr_set = false;
    if (!attr_set) {
        cudaFuncSetAttribute(attn_flash, cudaFuncAttributeMaxDynamicSharedMemorySize,
                             (2 * TILE_FLOATS + 8 * TN + TN + 2) * sizeof(float));
        attr_set = true;
    }

    // K1: w = u1*(in_state@Wq^T + bq) + u2
    {
        dim3 grid(Dd / 32, Bb / 32), block(16, 16);
        gemm_w<<<grid, block>>>(in_state, Wq, bq, Wc, Wa, w_ptr);
    }

    // K2: single-pass attention
    {
        size_t smem_bytes = (2 * TILE_FLOATS + 8 * TN + TN + 2) * sizeof(float);
        attn_flash<<<Bb, ATTN_THREADS, smem_bytes>>>(image, w_ptr);
    }

    // K3: out = pooled @ Wo^T + bo
    {
        dim3 grid(Ss / 32, Bb / 32), block(16, 16);
        gemm_out<<<grid, block>>>(pooled_ptr, Wo, bo, out);
    }
}

// round 4
// speedup vs baseline: 1.8744x; 1.8744x over previous
#include <cuda_runtime.h>
#include <math.h>
#include <stdint.h>

#define Bb 128
#define Ss 1024
#define Dd 512
#define Nn 784

#define TN 28          // n-tile width: 784 = 28 * 28
#define NTILES 28
#define ATHREADS 512   // 16 warps; warp w owns d-rows [32w, 32w+32)

// ---------------- scratch (no allocations allowed) ----------------
__device__ float g_u[2 * Dd];        // Wa @ Wc : [2D]  (atomic-accumulated)
__device__ float g_q[Bb * Dd];       // in_state @ Wq^T (atomic-accumulated)
__device__ float g_pooled[Bb * Dd];  // attention-pooled features

// ================= K0: init (zero g_q, g_u; out = bias) =================
// grid 193 x 1024 covers 65536 + 1024 + 131072 elements exactly.
__global__ void init_kernel(float* __restrict__ q, float* __restrict__ u,
                            float* __restrict__ out, const float* __restrict__ bo) {
    int i = blockIdx.x * 1024 + threadIdx.x;
    if (i < Bb * Dd) {
        q[i] = 0.f;
    } else if (i < Bb * Dd + 2 * Dd) {
        u[i - Bb * Dd] = 0.f;
    } else {
        int j = i - (Bb * Dd + 2 * Dd);
        out[j] = bo[j & (Ss - 1)];
    }
}

// ================= K1: u = Wa @ Wc (split over d, atomicAdd) =================
// grid (4, 32): j-chunk of 256 columns, 16 d-rows per CTA. 128 CTAs.
__global__ void u_kernel(const float* __restrict__ Wa, const float* __restrict__ Wc,
                         float* __restrict__ u) {
    int j = blockIdx.x * 256 + threadIdx.x;  // 0..2D-1
    int d0 = blockIdx.y * 16;
    float acc = 0.f;
#pragma unroll
    for (int d = d0; d < d0 + 16; d++) acc += Wa[d] * Wc[(size_t)d * (2 * Dd) + j];
    atomicAdd(&u[j], acc);
}

// ================= split-K NT GEMM: C[M,N] += A[M,K] @ Bm[N,K]^T =================
// grid (N/32, M/32, K/kslice); 256 threads; C pre-initialized (0 or bias).
__global__ void gemm_splitk(const float* __restrict__ A, const float* __restrict__ Bm,
                            float* __restrict__ C, int M, int N, int K, int kslice) {
    __shared__ float As[32][33];
    __shared__ float Bs[32][33];
    int tx = threadIdx.x, ty = threadIdx.y;
    int t = ty * 16 + tx;
    int row0 = blockIdx.y * 32, col0 = blockIdx.x * 32;
    int kbeg = blockIdx.z * kslice;
    float acc00 = 0.f, acc01 = 0.f, acc10 = 0.f, acc11 = 0.f;

    for (int k0 = kbeg; k0 < kbeg + kslice; k0 += 32) {
#pragma unroll
        for (int i = t; i < 32 * 32; i += 256) {
            int r = i >> 5, c = i & 31;
            As[r][c] = A[(size_t)(row0 + r) * K + k0 + c];
            Bs[r][c] = Bm[(size_t)(col0 + r) * K + k0 + c];
        }
        __syncthreads();
#pragma unroll
        for (int kk = 0; kk < 32; kk++) {
            float a0 = As[ty * 2][kk], a1 = As[ty * 2 + 1][kk];
            float b0 = Bs[tx * 2][kk], b1 = Bs[tx * 2 + 1][kk];
            acc00 += a0 * b0; acc01 += a0 * b1;
            acc10 += a1 * b0; acc11 += a1 * b1;
        }
        __syncthreads();
    }
    int r0 = row0 + ty * 2, c0 = col0 + tx * 2;
    atomicAdd(&C[(size_t)r0 * N + c0], acc00);
    atomicAdd(&C[(size_t)r0 * N + c0 + 1], acc01);
    atomicAdd(&C[(size_t)(r0 + 1) * N + c0], acc10);
    atomicAdd(&C[(size_t)(r0 + 1) * N + c0 + 1], acc11);
}

// ================= K3: register-resident single-pass flash attention =================
// One CTA (512 thr) per batch. Warp w owns d-rows [32w,32w+32); lane l<28 holds
// column n = t*28 + l of those rows in registers. No smem staging, no atomics.
// w[d] computed in prologue: u1[d]*(q[b,d]+bq[d]) + u2[d].
__global__ __launch_bounds__(ATHREADS, 1) void attn_flash(
    const float* __restrict__ image, const float* __restrict__ q,
    const float* __restrict__ u, const float* __restrict__ bq,
    float* __restrict__ pooled) {
    __shared__ float spart[16 * 29];  // padded: row stride 29 -> conflict-free column sums
    __shared__ float sp[32];
    __shared__ float sctl[2];

    const int b = blockIdx.x;
    const int lane = threadIdx.x & 31;
    const int warp = threadIdx.x >> 5;  // 0..15
    const int d0 = warp * 32;
    const bool act = (lane < TN);
    const float* imgb = image + (size_t)b * Dd * Nn + (size_t)d0 * Nn;

    // fused w: lane l holds w[b, d0+l]
    const int dg = d0 + lane;
    const float swv = u[dg] * (q[b * Dd + dg] + bq[dg]) + u[Dd + dg];

    float ra[32], rb[32], acc[32];
#pragma unroll
    for (int i = 0; i < 32; i++) acc[i] = 0.f;
    float m = -INFINITY, Zl = 0.f;

    // prologue: tile 0 -> ra
    {
        const float* p = imgb + lane;
#pragma unroll
        for (int i = 0; i < 32; i++) ra[i] = act ? __ldg(p + (size_t)i * Nn) : 0.f;
    }

#define PROCESS(REG)                                                               \
    {                                                                              \
        float a = 0.f;                                                             \
        _Pragma("unroll")                                                          \
        for (int i = 0; i < 32; i++)                                               \
            a += __shfl_sync(0xffffffffu, swv, i) * REG[i];                        \
        if (act) spart[warp * 29 + lane] = a;                                      \
        __syncthreads();                                                           \
        if (warp == 0) {                                                           \
            float v = 0.f;                                                         \
            _Pragma("unroll")                                                      \
            for (int r = 0; r < 16; r++) v += spart[r * 29 + lane];                \
            float vm = act ? v : -INFINITY;                                        \
            _Pragma("unroll")                                                      \
            for (int o = 16; o; o >>= 1)                                           \
                vm = fmaxf(vm, __shfl_xor_sync(0xffffffffu, vm, o));               \
            float newm = fmaxf(m, vm);                                             \
            float e = act ? __expf(v - newm) : 0.f;                                \
            sp[lane] = e;                                                          \
            float ts = e;                                                          \
            _Pragma("unroll")                                                      \
            for (int o = 16; o; o >>= 1) ts += __shfl_xor_sync(0xffffffffu, ts, o);\
            float sc = __expf(m - newm);                                           \
            Zl = Zl * sc + ts;                                                     \
            m = newm;                                                              \
            if (lane == 0) sctl[0] = sc;                                           \
        }                                                                          \
        __syncthreads();                                                           \
        {                                                                          \
            float sc = sctl[0];                                                    \
            float pw = sp[lane]; /* lanes 28-31 got e=0 */                         \
            _Pragma("unroll")                                                      \
            for (int i = 0; i < 32; i++) acc[i] = acc[i] * sc + pw * REG[i];       \
        }                                                                          \
    }

    for (int t = 0; t < NTILES; t += 2) {
        // prefetch tile t+1 -> rb (overlaps compute of tile t)
        {
            const float* p = imgb + (t + 1) * TN + lane;
#pragma unroll
            for (int i = 0; i < 32; i++) rb[i] = act ? __ldg(p + (size_t)i * Nn) : 0.f;
        }
        PROCESS(ra)
        // prefetch tile t+2 -> ra (overlaps compute of tile t+1)
        if (t + 2 < NTILES) {
            const float* p = imgb + (t + 2) * TN + lane;
#pragma unroll
            for (int i = 0; i < 32; i++) ra[i] = act ? __ldg(p + (size_t)i * Nn) : 0.f;
        }
        PROCESS(rb)
    }
#undef PROCESS

    if (warp == 0 && lane == 0) sctl[1] = Zl;
    __syncthreads();
    const float invZ = 1.f / sctl[1];

#pragma unroll
    for (int i = 0; i < 32; i++) {
        float v = acc[i];
#pragma unroll
        for (int o = 16; o; o >>= 1) v += __shfl_xor_sync(0xffffffffu, v, o);
        if (lane == 0) pooled[b * Dd + d0 + i] = v * invZ;
    }
}

// ---------------- launcher (5 graph nodes) ----------------
extern "C" void kernel_launch(void* const* d_in, const int* in_sizes, int n_in,
                              void* d_out, int out_size) {
    const float* in_state = (const float*)d_in[0];  // [B, S]
    const float* image    = (const float*)d_in[1];  // [B, D, N]
    const float* Wq       = (const float*)d_in[2];  // [D, S]
    const float* bq       = (const float*)d_in[3];  // [D]
    const float* Wc       = (const float*)d_in[4];  // [D, 2D]
    // d_in[5] = bc (cancels in softmax)
    const float* Wa       = (const float*)d_in[6];  // [1, D]
    // d_in[7] = ba (cancels in softmax)
    const float* Wo       = (const float*)d_in[8];  // [S, D]
    const float* bo       = (const float*)d_in[9];  // [S]
    float* out = (float*)d_out;                     // [B, S]

    float* u_ptr;      cudaGetSymbolAddress((void**)&u_ptr, g_u);
    float* q_ptr;      cudaGetSymbolAddress((void**)&q_ptr, g_q);
    float* pooled_ptr; cudaGetSymbolAddress((void**)&pooled_ptr, g_pooled);

    // K0: zero q,u; out = bias  (193*1024 = 197632 = 65536+1024+131072)
    init_kernel<<<193, 1024>>>(q_ptr, u_ptr, out, bo);

    // K1: u = Wa @ Wc
    {
        dim3 grid(4, 32);
        u_kernel<<<grid, 256>>>(Wa, Wc, u_ptr);
    }

    // K2: q += in_state @ Wq^T (split-K x8 -> 512 CTAs)
    {
        dim3 grid(Dd / 32, Bb / 32, 8), block(16, 16);
        gemm_splitk<<<grid, block>>>(in_state, Wq, q_ptr, Bb, Dd, Ss, Ss / 8);
    }

    // K3: register-resident flash attention (w fused in prologue)
    attn_flash<<<Bb, ATHREADS>>>(image, q_ptr, u_ptr, bq, pooled_ptr);

    // K4: out += pooled @ Wo^T (split-K x4 -> 512 CTAs, bias already in out)
    {
        dim3 grid(Ss / 32, Bb / 32, 4), block(16, 16);
        gemm_splitk<<<grid, block>>>(pooled_ptr, Wo, out, Bb, Ss, Dd, Dd / 4);
    }
}

// round 6
// speedup vs baseline: 1.9461x; 1.0383x over previous
#include <cuda_runtime.h>
#include <math.h>
#include <stdint.h>

#define Bb 128
#define Ss 1024
#define Dd 512
#define Nn 784

#define TN 28          // n-tile width: 784 = 28 * 28
#define NTILES 28
#define ATHREADS 512   // 16 warps; warp w owns d-rows [32w, 32w+32)
#define KSPLIT 8       // q-GEMM split-K factor

// ---------------- scratch (no allocations allowed) ----------------
__device__ float g_qpart[KSPLIT * Bb * Dd];   // q split-K partials (2 MB)
__device__ float g_upart[KSPLIT * 2 * Dd];    // u partials: [p][1024]
__device__ float g_pooled[Bb * Dd];           // attention-pooled features

// ================= K1: heterogeneous prep kernel (one launch) =================
// CTA [0,512):   q split-K partials:  g_qpart[z][b_tile][d_tile]
// CTA [512,544): u partials:          g_upart[kchunk][col]
// CTA [544,1056): out bias init:      out[j] = bo[j % Ss]
__global__ void prep_kernel(const float* __restrict__ in_state,  // [B,S]
                            const float* __restrict__ Wq,        // [D,S]
                            const float* __restrict__ Wa,        // [D]
                            const float* __restrict__ Wc,        // [D,2D]
                            const float* __restrict__ bo,        // [S]
                            float* __restrict__ out,             // [B,S]
                            float* __restrict__ qpart,
                            float* __restrict__ upart) {
    const int cta = blockIdx.x;
    const int tid = threadIdx.x;  // 256 threads

    if (cta < 512) {
        // ---- q split-K: C_z[M=128, N=512] = A[:, z*128:(z+1)*128] @ Wq_slice^T ----
        __shared__ float As[32][33];
        __shared__ float Bs[32][33];
        const int z = cta >> 6;           // 0..7
        const int rem = cta & 63;
        const int bx = rem & 15;          // D tile (16)
        const int by = rem >> 4;          // B tile (4)
        const int tx = tid & 15, ty = tid >> 4;
        const int row0 = by * 32, col0 = bx * 32;
        const int kbeg = z * (Ss / KSPLIT);
        float acc00 = 0.f, acc01 = 0.f, acc10 = 0.f, acc11 = 0.f;

        for (int k0 = kbeg; k0 < kbeg + Ss / KSPLIT; k0 += 32) {
#pragma unroll
            for (int i = tid; i < 32 * 32; i += 256) {
                int r = i >> 5, c = i & 31;
                As[r][c] = in_state[(size_t)(row0 + r) * Ss + k0 + c];
                Bs[r][c] = Wq[(size_t)(col0 + r) * Ss + k0 + c];
            }
            __syncthreads();
#pragma unroll
            for (int kk = 0; kk < 32; kk++) {
                float a0 = As[ty * 2][kk], a1 = As[ty * 2 + 1][kk];
                float b0 = Bs[tx * 2][kk], b1 = Bs[tx * 2 + 1][kk];
                acc00 += a0 * b0; acc01 += a0 * b1;
                acc10 += a1 * b0; acc11 += a1 * b1;
            }
            __syncthreads();
        }
        int r0 = row0 + ty * 2, c0 = col0 + tx * 2;
        float* base = qpart + (size_t)z * Bb * Dd;
        base[(size_t)r0 * Dd + c0]           = acc00;
        base[(size_t)r0 * Dd + c0 + 1]       = acc01;
        base[(size_t)(r0 + 1) * Dd + c0]     = acc10;
        base[(size_t)(r0 + 1) * Dd + c0 + 1] = acc11;
    } else if (cta < 544) {
        // ---- u partials: 4 col-chunks x 8 k-chunks ----
        const int local = cta - 512;
        const int colchunk = local & 3;   // 256 cols each
        const int kchunk = local >> 2;    // 64 d-rows each
        const int col = colchunk * 256 + tid;
        const int dbeg = kchunk * 64;
        float acc = 0.f;
#pragma unroll 8
        for (int d = dbeg; d < dbeg + 64; d++)
            acc += Wa[d] * Wc[(size_t)d * (2 * Dd) + col];
        upart[kchunk * (2 * Dd) + col] = acc;
    } else {
        // ---- out bias init ----
        const int j = (cta - 544) * 256 + tid;  // covers 512*256 = 131072 exactly
        out[j] = bo[j & (Ss - 1)];
    }
}

// ================= K2: register-resident flash attention, all-warp softmax =================
// One CTA (512 thr) per batch. Warp w owns d-rows [32w,32w+32); lane l<28 holds
// column n = t*28 + l in registers. One barrier per tile; softmax computed
// redundantly (identically) by every warp. w[d] = u1[d]*(q[b,d]+bq[d]) + u2[d],
// with q and u summed from split-K partials in the prologue.
__global__ __launch_bounds__(ATHREADS, 1) void attn_flash(
    const float* __restrict__ image, const float* __restrict__ qpart,
    const float* __restrict__ upart, const float* __restrict__ bq,
    float* __restrict__ pooled) {
    // Padded +32: redundant lanes 28-31 read up to index 16*29+2 per buffer;
    // keep ALL reads inside the declared array (R5 crash: 3-float OOB read
    // fell outside the CTA smem window).
    __shared__ float spart[2][16 * 29 + 32];

    const int b = blockIdx.x;
    const int lane = threadIdx.x & 31;
    const int warp = threadIdx.x >> 5;  // 0..15
    const int d0 = warp * 32;
    const int dg = d0 + lane;           // < 512 always
    const bool act = (lane < TN);
    const float* imgb = image + (size_t)b * Dd * Nn + (size_t)d0 * Nn;

    // ---- prologue: reduce split-K partials -> fused logit weight swv ----
    float qsum = 0.f, u1 = 0.f, u2 = 0.f;
#pragma unroll
    for (int p = 0; p < KSPLIT; p++) {
        qsum += qpart[((size_t)p * Bb + b) * Dd + dg];
        u1 += upart[p * (2 * Dd) + dg];
        u2 += upart[p * (2 * Dd) + Dd + dg];
    }
    const float swv = u1 * (qsum + bq[dg]) + u2;

    float ra[32], rb[32], acc[32];
#pragma unroll
    for (int i = 0; i < 32; i++) acc[i] = 0.f;
    float m = -INFINITY, Zl = 0.f;

    // prologue: tile 0 -> ra
    {
        const float* p = imgb + lane;
#pragma unroll
        for (int i = 0; i < 32; i++) ra[i] = act ? __ldg(p + (size_t)i * Nn) : 0.f;
    }

#define PROCESS(REG, PAR)                                                          \
    {                                                                              \
        float a = 0.f;                                                             \
        _Pragma("unroll")                                                          \
        for (int i = 0; i < 32; i++)                                               \
            a += __shfl_sync(0xffffffffu, swv, i) * REG[i];                        \
        if (act) spart[PAR][warp * 29 + lane] = a;                                 \
        __syncthreads();                                                           \
        float v = 0.f;                                                             \
        _Pragma("unroll")                                                          \
        for (int r = 0; r < 16; r++) v += spart[PAR][r * 29 + lane];               \
        float vm = act ? v : -INFINITY;                                            \
        _Pragma("unroll")                                                          \
        for (int o = 16; o; o >>= 1)                                               \
            vm = fmaxf(vm, __shfl_xor_sync(0xffffffffu, vm, o));                   \
        float newm = fmaxf(m, vm);                                                 \
        float e = act ? __expf(v - newm) : 0.f;                                    \
        float ts = e;                                                              \
        _Pragma("unroll")                                                          \
        for (int o = 16; o; o >>= 1) ts += __shfl_xor_sync(0xffffffffu, ts, o);    \
        float sc = __expf(m - newm);                                               \
        Zl = Zl * sc + ts;                                                         \
        m = newm;                                                                  \
        _Pragma("unroll")                                                          \
        for (int i = 0; i < 32; i++) acc[i] = acc[i] * sc + e * REG[i];            \
    }

    for (int t = 0; t < NTILES; t += 2) {
        // prefetch tile t+1 -> rb (overlaps compute of tile t)
        {
            const float* p = imgb + (t + 1) * TN + lane;
#pragma unroll
            for (int i = 0; i < 32; i++) rb[i] = act ? __ldg(p + (size_t)i * Nn) : 0.f;
        }
        PROCESS(ra, 0)
        // prefetch tile t+2 -> ra (overlaps compute of tile t+1)
        if (t + 2 < NTILES) {
            const float* p = imgb + (t + 2) * TN + lane;
#pragma unroll
            for (int i = 0; i < 32; i++) ra[i] = act ? __ldg(p + (size_t)i * Nn) : 0.f;
        }
        PROCESS(rb, 1)
    }
#undef PROCESS

    const float invZ = 1.f / Zl;  // identical in every warp
#pragma unroll
    for (int i = 0; i < 32; i++) {
        float v = acc[i];
#pragma unroll
        for (int o = 16; o; o >>= 1) v += __shfl_xor_sync(0xffffffffu, v, o);
        if (lane == 0) pooled[b * Dd + d0 + i] = v * invZ;
    }
}

// ================= K3: out += pooled @ Wo^T (split-K x4, atomic; bias pre-set) ==========
__global__ void gemm_out(const float* __restrict__ A,   // pooled [B,D]
                         const float* __restrict__ Bm,  // Wo [S,D]
                         float* __restrict__ C) {       // out [B,S] (bias-initialized)
    __shared__ float As[32][33];
    __shared__ float Bs[32][33];
    int tx = threadIdx.x, ty = threadIdx.y;
    int t = ty * 16 + tx;
    int row0 = blockIdx.y * 32, col0 = blockIdx.x * 32;
    int kbeg = blockIdx.z * (Dd / 4);
    float acc00 = 0.f, acc01 = 0.f, acc10 = 0.f, acc11 = 0.f;

    for (int k0 = kbeg; k0 < kbeg + Dd / 4; k0 += 32) {
#pragma unroll
        for (int i = t; i < 32 * 32; i += 256) {
            int r = i >> 5, c = i & 31;
            As[r][c] = A[(size_t)(row0 + r) * Dd + k0 + c];
            Bs[r][c] = Bm[(size_t)(col0 + r) * Dd + k0 + c];
        }
        __syncthreads();
#pragma unroll
        for (int kk = 0; kk < 32; kk++) {
            float a0 = As[ty * 2][kk], a1 = As[ty * 2 + 1][kk];
            float b0 = Bs[tx * 2][kk], b1 = Bs[tx * 2 + 1][kk];
            acc00 += a0 * b0; acc01 += a0 * b1;
            acc10 += a1 * b0; acc11 += a1 * b1;
        }
        __syncthreads();
    }
    int r0 = row0 + ty * 2, c0 = col0 + tx * 2;
    atomicAdd(&C[(size_t)r0 * Ss + c0], acc00);
    atomicAdd(&C[(size_t)r0 * Ss + c0 + 1], acc01);
    atomicAdd(&C[(size_t)(r0 + 1) * Ss + c0], acc10);
    atomicAdd(&C[(size_t)(r0 + 1) * Ss + c0 + 1], acc11);
}

// ---------------- launcher (3 graph nodes) ----------------
extern "C" void kernel_launch(void* const* d_in, const int* in_sizes, int n_in,
                              void* d_out, int out_size) {
    const float* in_state = (const float*)d_in[0];  // [B, S]
    const float* image    = (const float*)d_in[1];  // [B, D, N]
    const float* Wq       = (const float*)d_in[2];  // [D, S]
    const float* bq       = (const float*)d_in[3];  // [D]
    const float* Wc       = (const float*)d_in[4];  // [D, 2D]
    // d_in[5] = bc (cancels in softmax)
    const float* Wa       = (const float*)d_in[6];  // [1, D]
    // d_in[7] = ba (cancels in softmax)
    const float* Wo       = (const float*)d_in[8];  // [S, D]
    const float* bo       = (const float*)d_in[9];  // [S]
    float* out = (float*)d_out;                     // [B, S]

    float* qpart_ptr;  cudaGetSymbolAddress((void**)&qpart_ptr, g_qpart);
    float* upart_ptr;  cudaGetSymbolAddress((void**)&upart_ptr, g_upart);
    float* pooled_ptr; cudaGetSymbolAddress((void**)&pooled_ptr, g_pooled);

    // K1: q-partials + u-partials + out-bias, one heterogeneous launch
    prep_kernel<<<1056, 256>>>(in_state, Wq, Wa, Wc, bo, out, qpart_ptr, upart_ptr);

    // K2: flash attention (partials reduced in prologue)
    attn_flash<<<Bb, ATHREADS>>>(image, qpart_ptr, upart_ptr, bq, pooled_ptr);

    // K3: out += pooled @ Wo^T (split-K x4)
    {
        dim3 grid(Ss / 32, Bb / 32, 4), block(16, 16);
        gemm_out<<<grid, block>>>(pooled_ptr, Wo, out);
    }
}